// round 3
// baseline (speedup 1.0000x reference)
#include <cuda_runtime.h>
#include <stdint.h>

#define R_TOT 524288
#define NE    33554432

struct Params {
    float s_x, zp_x, s_h, zp_h, s_c, zp_c, s_cat, zp_cat;
    float alpha[4];
    float bdq[256];
    int   zpw_i[4], zpc_i;
    float sG[4], zpG[4], sA[4], zpA[4];
    float s_fc, zp_fc, s_ic, zp_ic, s_cn, zp_cn, s_t, zp_t, s_hn, zp_hn;
};

__device__ Params   g_p;
__device__ unsigned g_mm[22];          // 11 (min,max) encoded-float slots
__device__ int8_t   g_wq[256 * 128];   // quantized weight codes
__device__ int      g_const[256];      // per-output zero-point correction
__device__ float    g_G[134217728];    // gate pre-activations [4][NE]
__device__ int8_t   g_act[4][NE];      // i,f,o,cg activation codes
__device__ int8_t   g_cq[NE];          // c_prev codes
__device__ int8_t   g_tq[NE];          // tanh(c_next) codes

// ---------- helpers ----------
__device__ __forceinline__ unsigned fenc(float f) {
    unsigned u = __float_as_uint(f);
    return (u & 0x80000000u) ? ~u : (u | 0x80000000u);
}
__device__ __forceinline__ float fdec(unsigned u) {
    return __uint_as_float((u & 0x80000000u) ? (u & 0x7fffffffu) : ~u);
}
__device__ __forceinline__ float quant_q(float v, float s, float zp) {
    float q = rintf(__fdiv_rn(v, s)) + zp;
    return fminf(fmaxf(q, -128.f), 127.f);
}
__device__ __forceinline__ float fqv(float v, float s, float zp) {
    return __fmul_rn(quant_q(v, s, zp) - zp, s);
}
__device__ __forceinline__ void mkparams(float mnr, float mxr, float* s, float* zp) {
    float mn = fminf(mnr, 0.f), mx = fmaxf(mxr, 0.f);
    float sc = fmaxf(__fdiv_rn(mx - mn, 255.f), 1e-8f);
    float z  = rintf(-128.f - __fdiv_rn(mn, sc));
    *s = sc; *zp = fminf(fmaxf(z, -128.f), 127.f);
}
__device__ __forceinline__ float hsig(float v) {
    return fminf(fmaxf(__fadd_rn(__fdiv_rn(v, 6.f), 0.5f), 0.f), 1.f);
}
__device__ __forceinline__ float htanh(float v) { return fminf(fmaxf(v, -1.f), 1.f); }

__device__ __forceinline__ void block_minmax(float mn, float mx, unsigned* gmin, unsigned* gmax) {
    #pragma unroll
    for (int o = 16; o; o >>= 1) {
        mn = fminf(mn, __shfl_xor_sync(0xffffffffu, mn, o));
        mx = fmaxf(mx, __shfl_xor_sync(0xffffffffu, mx, o));
    }
    __shared__ float smn[8], smx[8];
    int w = threadIdx.x >> 5, nw = blockDim.x >> 5;
    __syncthreads();
    if ((threadIdx.x & 31) == 0) { smn[w] = mn; smx[w] = mx; }
    __syncthreads();
    if (threadIdx.x == 0) {
        for (int i = 1; i < nw; i++) { mn = fminf(mn, smn[i]); mx = fmaxf(mx, smx[i]); }
        atomicMin(gmin, fenc(mn));
        atomicMax(gmax, fenc(mx));
    }
    __syncthreads();
}

__device__ __forceinline__ float2 block_reduce_pair(float mn, float mx) {
    #pragma unroll
    for (int o = 16; o; o >>= 1) {
        mn = fminf(mn, __shfl_xor_sync(0xffffffffu, mn, o));
        mx = fmaxf(mx, __shfl_xor_sync(0xffffffffu, mx, o));
    }
    __shared__ float smn[8], smx[8];
    __shared__ float2 res;
    int w = threadIdx.x >> 5, nw = blockDim.x >> 5;
    __syncthreads();
    if ((threadIdx.x & 31) == 0) { smn[w] = mn; smx[w] = mx; }
    __syncthreads();
    if (threadIdx.x == 0) {
        for (int i = 1; i < nw; i++) { mn = fminf(mn, smn[i]); mx = fmaxf(mx, smx[i]); }
        res = make_float2(mn, mx);
    }
    __syncthreads();
    return res;
}

// ---------- K0: reset reduction slots ----------
__global__ void k_init() {
    int t = threadIdx.x;
    if (t < 11) { g_mm[2 * t] = fenc(1e30f); g_mm[2 * t + 1] = fenc(-1e30f); }
}

// ---------- K1: minmax of x, h, c ----------
__global__ void k_minmax3(const float* __restrict__ x, const float* __restrict__ h,
                          const float* __restrict__ c) {
    const float* arrs[3] = {x, h, c};
    for (int a = 0; a < 3; a++) {
        float mn = 1e30f, mx = -1e30f;
        const float4* p = (const float4*)arrs[a];
        for (long i = blockIdx.x * blockDim.x + threadIdx.x; i < NE / 4;
             i += (long)gridDim.x * blockDim.x) {
            float4 v = p[i];
            mn = fminf(fminf(fminf(mn, v.x), v.y), fminf(v.z, v.w));
            mx = fmaxf(fmaxf(fmaxf(mx, v.x), v.y), fmaxf(v.z, v.w));
        }
        block_minmax(mn, mx, &g_mm[2 * a], &g_mm[2 * a + 1]);
    }
}

// ---------- K2: scalar params + weight/bias quantization (1 block) ----------
__global__ void k_params(const float* __restrict__ Wi, const float* __restrict__ bi,
                         const float* __restrict__ Wf, const float* __restrict__ bf,
                         const float* __restrict__ Wo, const float* __restrict__ bo,
                         const float* __restrict__ Wc, const float* __restrict__ bc) {
    __shared__ float sw, zw, sb, zb;
    int t = threadIdx.x;
    if (t == 0) {
        mkparams(fdec(g_mm[0]), fdec(g_mm[1]), &g_p.s_x, &g_p.zp_x);
        mkparams(fdec(g_mm[2]), fdec(g_mm[3]), &g_p.s_h, &g_p.zp_h);
        mkparams(fdec(g_mm[4]), fdec(g_mm[5]), &g_p.s_c, &g_p.zp_c);
        float xlo = fqv(fdec(g_mm[0]), g_p.s_x, g_p.zp_x);
        float xhi = fqv(fdec(g_mm[1]), g_p.s_x, g_p.zp_x);
        float hlo = fqv(fdec(g_mm[2]), g_p.s_h, g_p.zp_h);
        float hhi = fqv(fdec(g_mm[3]), g_p.s_h, g_p.zp_h);
        mkparams(fminf(xlo, hlo), fmaxf(xhi, hhi), &g_p.s_cat, &g_p.zp_cat);
        g_p.zpc_i = (int)g_p.zp_cat;
    }
    __syncthreads();
    const float* Wg[4] = {Wi, Wf, Wo, Wc};
    const float* bg[4] = {bi, bf, bo, bc};
    for (int g = 0; g < 4; g++) {
        float mn = 1e30f, mx = -1e30f;
        for (int i = t; i < 8192; i += 256) {
            float v = Wg[g][i];
            mn = fminf(mn, v); mx = fmaxf(mx, v);
        }
        float2 m = block_reduce_pair(mn, mx);
        if (t == 0) {
            mkparams(m.x, m.y, &sw, &zw);
            g_p.alpha[g] = __fmul_rn(g_p.s_cat, sw);
            g_p.zpw_i[g] = (int)zw;
        }
        __syncthreads();
        for (int i = t; i < 8192; i += 256)
            g_wq[g * 8192 + i] = (int8_t)(int)quant_q(Wg[g][i], sw, zw);
        mn = (t < 64) ? bg[g][t] : 1e30f;
        mx = (t < 64) ? bg[g][t] : -1e30f;
        m = block_reduce_pair(mn, mx);
        if (t == 0) mkparams(m.x, m.y, &sb, &zb);
        __syncthreads();
        if (t < 64) g_p.bdq[g * 64 + t] = fqv(bg[g][t], sb, zb);
        __syncthreads();
    }
    {
        int s = 0;
        const int8_t* wr = &g_wq[t * 128];
        for (int k = 0; k < 128; k++) s += wr[k];
        int g = t >> 6;
        g_const[t] = -g_p.zpc_i * s + 128 * g_p.zpc_i * g_p.zpw_i[g];
    }
}

// ---------- K2b: quantize c_prev to codes ----------
__global__ void k_quantc(const float* __restrict__ c) {
    float s = g_p.s_c, z = g_p.zp_c;
    for (long i = blockIdx.x * blockDim.x + threadIdx.x; i < NE / 4;
         i += (long)gridDim.x * blockDim.x) {
        float4 v = ((const float4*)c)[i];
        char4 q;
        q.x = (int8_t)(int)quant_q(v.x, s, z);
        q.y = (int8_t)(int)quant_q(v.y, s, z);
        q.z = (int8_t)(int)quant_q(v.z, s, z);
        q.w = (int8_t)(int)quant_q(v.w, s, z);
        ((char4*)g_cq)[i] = q;
    }
}

// ---------- K3: int8 GEMM (dp4a), gate minmax, store G ----------
__global__ void __launch_bounds__(256) k_gemm(const float* __restrict__ X,
                                              const float* __restrict__ H) {
    __shared__ uint32_t rsm[8][33];
    __shared__ int rowsum[8];
    int t = threadIdx.x, lane = t & 31, wrp = t >> 5;
    int g = t >> 6, hcol = t & 63;
    // weight row for this output, in registers
    int wv[32];
    const int* wq32 = (const int*)g_wq;
    #pragma unroll
    for (int w = 0; w < 32; w++) wv[w] = wq32[t * 32 + w];
    float al = g_p.alpha[g], bo = g_p.bdq[t];
    int   zw = g_p.zpw_i[g], co = g_const[t];
    float sx = g_p.s_x, zx = g_p.zp_x, sh = g_p.s_h, zh = g_p.zp_h;
    float sc = g_p.s_cat, zc = g_p.zp_cat;
    float mn = 1e30f, mx = -1e30f;

    for (long tile = blockIdx.x; tile < R_TOT / 8; tile += gridDim.x) {
        long r0 = tile * 8;
        // warp wrp quantizes row r0+wrp (128 cat codes)
        {
            long r = r0 + wrp;
            float4 v = (lane < 16) ? ((const float4*)X)[r * 16 + lane]
                                   : ((const float4*)H)[r * 16 + lane - 16];
            float s0 = (lane < 16) ? sx : sh, z0 = (lane < 16) ? zx : zh;
            int q0 = (int)quant_q(fqv(v.x, s0, z0), sc, zc);
            int q1 = (int)quant_q(fqv(v.y, s0, z0), sc, zc);
            int q2 = (int)quant_q(fqv(v.z, s0, z0), sc, zc);
            int q3 = (int)quant_q(fqv(v.w, s0, z0), sc, zc);
            uint32_t pk = (uint32_t)(q0 & 255) | ((uint32_t)(q1 & 255) << 8) |
                          ((uint32_t)(q2 & 255) << 16) | ((uint32_t)(q3 & 255) << 24);
            int sum = q0 + q1 + q2 + q3;
            #pragma unroll
            for (int o = 16; o; o >>= 1) sum += __shfl_xor_sync(0xffffffffu, sum, o);
            rsm[wrp][lane] = pk;
            if (lane == 0) rowsum[wrp] = sum;
        }
        __syncthreads();
        #pragma unroll
        for (int rr = 0; rr < 8; rr++) {
            int acc = 0;
            #pragma unroll
            for (int w = 0; w < 32; w++) acc = __dp4a((int)rsm[rr][w], wv[w], acc);
            int S = acc - zw * rowsum[rr] + co;
            float G = __fadd_rn(__fmul_rn((float)S, al), bo);
            mn = fminf(mn, G); mx = fmaxf(mx, G);
            g_G[(size_t)g * NE + (r0 + rr) * 64 + hcol] = G;
        }
        __syncthreads();
    }
    // per-warp reduce (each warp is gate-homogeneous), then atomics
    #pragma unroll
    for (int o = 16; o; o >>= 1) {
        mn = fminf(mn, __shfl_xor_sync(0xffffffffu, mn, o));
        mx = fmaxf(mx, __shfl_xor_sync(0xffffffffu, mx, o));
    }
    if (lane == 0) {
        atomicMin(&g_mm[6 + 2 * g], fenc(mn));
        atomicMax(&g_mm[7 + 2 * g], fenc(mx));
    }
}

// ---------- K4: gate + activation params ----------
__global__ void k_p2() {
    for (int g = 0; g < 4; g++) {
        float mn = fdec(g_mm[6 + 2 * g]), mx = fdec(g_mm[7 + 2 * g]);
        mkparams(mn, mx, &g_p.sG[g], &g_p.zpG[g]);
        float lo = fqv(mn, g_p.sG[g], g_p.zpG[g]);
        float hi = fqv(mx, g_p.sG[g], g_p.zpG[g]);
        float amin, amax;
        if (g < 3) { amin = hsig(lo); amax = hsig(hi); }
        else       { amin = htanh(lo); amax = htanh(hi); }
        mkparams(amin, amax, &g_p.sA[g], &g_p.zpA[g]);
    }
}

// ---------- K5: activations -> codes; minmax(f*c), minmax(i*cg) ----------
__global__ void k_act() {
    float sG[4], zG[4], sA[4], zA[4];
    #pragma unroll
    for (int g = 0; g < 4; g++) { sG[g] = g_p.sG[g]; zG[g] = g_p.zpG[g];
                                  sA[g] = g_p.sA[g]; zA[g] = g_p.zpA[g]; }
    float scc = g_p.s_c, zcc = g_p.zp_c;
    float mn1 = 1e30f, mx1 = -1e30f, mn2 = 1e30f, mx2 = -1e30f;
    for (long i = blockIdx.x * blockDim.x + threadIdx.x; i < NE / 4;
         i += (long)gridDim.x * blockDim.x) {
        float av[4][4];
        #pragma unroll
        for (int g = 0; g < 4; g++) {
            float4 G4 = ((const float4*)(g_G + (size_t)g * NE))[i];
            float gv[4] = {G4.x, G4.y, G4.z, G4.w};
            char4 q;
            int8_t* qq = (int8_t*)&q;
            #pragma unroll
            for (int j = 0; j < 4; j++) {
                float v = fqv(gv[j], sG[g], zG[g]);
                float a = (g < 3) ? hsig(v) : htanh(v);
                int code = (int)quant_q(a, sA[g], zA[g]);
                qq[j] = (int8_t)code;
                av[g][j] = __fmul_rn((float)code - zA[g], sA[g]);
            }
            ((char4*)g_act[g])[i] = q;
        }
        char4 cq = ((const char4*)g_cq)[i];
        int cc[4] = {cq.x, cq.y, cq.z, cq.w};
        #pragma unroll
        for (int j = 0; j < 4; j++) {
            float cd = __fmul_rn((float)cc[j] - zcc, scc);
            float fc = __fmul_rn(av[1][j], cd);
            float ic = __fmul_rn(av[0][j], av[3][j]);
            mn1 = fminf(mn1, fc); mx1 = fmaxf(mx1, fc);
            mn2 = fminf(mn2, ic); mx2 = fmaxf(mx2, ic);
        }
    }
    block_minmax(mn1, mx1, &g_mm[14], &g_mm[15]);
    block_minmax(mn2, mx2, &g_mm[16], &g_mm[17]);
}

// ---------- K6 ----------
__global__ void k_p3() {
    mkparams(fdec(g_mm[14]), fdec(g_mm[15]), &g_p.s_fc, &g_p.zp_fc);
    mkparams(fdec(g_mm[16]), fdec(g_mm[17]), &g_p.s_ic, &g_p.zp_ic);
}

// ---------- K7: minmax of fq(fc)+fq(ic) ----------
__global__ void k_pre() {
    float sAi = g_p.sA[0], zAi = g_p.zpA[0], sAf = g_p.sA[1], zAf = g_p.zpA[1];
    float sAg = g_p.sA[3], zAg = g_p.zpA[3], scc = g_p.s_c, zcc = g_p.zp_c;
    float sfc = g_p.s_fc, zfc = g_p.zp_fc, sic = g_p.s_ic, zic = g_p.zp_ic;
    float mn = 1e30f, mx = -1e30f;
    for (long i = blockIdx.x * blockDim.x + threadIdx.x; i < NE / 4;
         i += (long)gridDim.x * blockDim.x) {
        char4 qi = ((const char4*)g_act[0])[i];
        char4 qf = ((const char4*)g_act[1])[i];
        char4 qg = ((const char4*)g_act[3])[i];
        char4 qc = ((const char4*)g_cq)[i];
        int ii[4] = {qi.x, qi.y, qi.z, qi.w}, ff[4] = {qf.x, qf.y, qf.z, qf.w};
        int gg[4] = {qg.x, qg.y, qg.z, qg.w}, cc[4] = {qc.x, qc.y, qc.z, qc.w};
        #pragma unroll
        for (int j = 0; j < 4; j++) {
            float fv = __fmul_rn((float)ff[j] - zAf, sAf);
            float iv = __fmul_rn((float)ii[j] - zAi, sAi);
            float gv = __fmul_rn((float)gg[j] - zAg, sAg);
            float cd = __fmul_rn((float)cc[j] - zcc, scc);
            float fcv = fqv(__fmul_rn(fv, cd), sfc, zfc);
            float icv = fqv(__fmul_rn(iv, gv), sic, zic);
            float pre = __fadd_rn(fcv, icv);
            mn = fminf(mn, pre); mx = fmaxf(mx, pre);
        }
    }
    block_minmax(mn, mx, &g_mm[18], &g_mm[19]);
}

// ---------- K8 ----------
__global__ void k_p4() {
    float mn = fdec(g_mm[18]), mx = fdec(g_mm[19]);
    mkparams(mn, mx, &g_p.s_cn, &g_p.zp_cn);
    float lo = htanh(fqv(mn, g_p.s_cn, g_p.zp_cn));
    float hi = htanh(fqv(mx, g_p.s_cn, g_p.zp_cn));
    mkparams(lo, hi, &g_p.s_t, &g_p.zp_t);
}

// ---------- K9: write c_next, store t codes, minmax(o*t) ----------
__global__ void k_cnext(float* __restrict__ out_c) {
    float sAi = g_p.sA[0], zAi = g_p.zpA[0], sAf = g_p.sA[1], zAf = g_p.zpA[1];
    float sAo = g_p.sA[2], zAo = g_p.zpA[2], sAg = g_p.sA[3], zAg = g_p.zpA[3];
    float scc = g_p.s_c, zcc = g_p.zp_c;
    float sfc = g_p.s_fc, zfc = g_p.zp_fc, sic = g_p.s_ic, zic = g_p.zp_ic;
    float scn = g_p.s_cn, zcn = g_p.zp_cn, st = g_p.s_t, zt = g_p.zp_t;
    float mn = 1e30f, mx = -1e30f;
    for (long i = blockIdx.x * blockDim.x + threadIdx.x; i < NE / 4;
         i += (long)gridDim.x * blockDim.x) {
        char4 qi = ((const char4*)g_act[0])[i];
        char4 qf = ((const char4*)g_act[1])[i];
        char4 qo = ((const char4*)g_act[2])[i];
        char4 qg = ((const char4*)g_act[3])[i];
        char4 qc = ((const char4*)g_cq)[i];
        int ii[4] = {qi.x, qi.y, qi.z, qi.w}, ff[4] = {qf.x, qf.y, qf.z, qf.w};
        int oo[4] = {qo.x, qo.y, qo.z, qo.w}, gg[4] = {qg.x, qg.y, qg.z, qg.w};
        int cc[4] = {qc.x, qc.y, qc.z, qc.w};
        float4 outc;
        float* oc = (float*)&outc;
        char4 tq4;
        int8_t* tqq = (int8_t*)&tq4;
        #pragma unroll
        for (int j = 0; j < 4; j++) {
            float fv = __fmul_rn((float)ff[j] - zAf, sAf);
            float iv = __fmul_rn((float)ii[j] - zAi, sAi);
            float gv = __fmul_rn((float)gg[j] - zAg, sAg);
            float cd = __fmul_rn((float)cc[j] - zcc, scc);
            float fcv = fqv(__fmul_rn(fv, cd), sfc, zfc);
            float icv = fqv(__fmul_rn(iv, gv), sic, zic);
            float pre = __fadd_rn(fcv, icv);
            float cn = fqv(pre, scn, zcn);
            oc[j] = cn;
            int tcode = (int)quant_q(htanh(cn), st, zt);
            tqq[j] = (int8_t)tcode;
            float tv = __fmul_rn((float)tcode - zt, st);
            float ov = __fmul_rn((float)oo[j] - zAo, sAo);
            float hp = __fmul_rn(ov, tv);
            mn = fminf(mn, hp); mx = fmaxf(mx, hp);
        }
        ((float4*)out_c)[i] = outc;
        ((char4*)g_tq)[i] = tq4;
    }
    block_minmax(mn, mx, &g_mm[20], &g_mm[21]);
}

// ---------- K10 ----------
__global__ void k_p5() {
    mkparams(fdec(g_mm[20]), fdec(g_mm[21]), &g_p.s_hn, &g_p.zp_hn);
}

// ---------- K11: h_next ----------
__global__ void k_hnext(float* __restrict__ out_h) {
    float sAo = g_p.sA[2], zAo = g_p.zpA[2], st = g_p.s_t, zt = g_p.zp_t;
    float shn = g_p.s_hn, zhn = g_p.zp_hn;
    for (long i = blockIdx.x * blockDim.x + threadIdx.x; i < NE / 4;
         i += (long)gridDim.x * blockDim.x) {
        char4 qo = ((const char4*)g_act[2])[i];
        char4 qt = ((const char4*)g_tq)[i];
        int oo[4] = {qo.x, qo.y, qo.z, qo.w}, tt[4] = {qt.x, qt.y, qt.z, qt.w};
        float4 outh;
        float* oh = (float*)&outh;
        #pragma unroll
        for (int j = 0; j < 4; j++) {
            float ov = __fmul_rn((float)oo[j] - zAo, sAo);
            float tv = __fmul_rn((float)tt[j] - zt, st);
            oh[j] = fqv(__fmul_rn(ov, tv), shn, zhn);
        }
        ((float4*)out_h)[i] = outh;
    }
}

extern "C" void kernel_launch(void* const* d_in, const int* in_sizes, int n_in,
                              void* d_out, int out_size) {
    const float* x  = (const float*)d_in[0];
    const float* h  = (const float*)d_in[1];
    const float* c  = (const float*)d_in[2];
    const float* Wi = (const float*)d_in[3];
    const float* bi = (const float*)d_in[4];
    const float* Wf = (const float*)d_in[5];
    const float* bf = (const float*)d_in[6];
    const float* Wo = (const float*)d_in[7];
    const float* bo = (const float*)d_in[8];
    const float* Wc = (const float*)d_in[9];
    const float* bc = (const float*)d_in[10];
    float* out_h = (float*)d_out;
    float* out_c = (float*)d_out + NE;

    k_init<<<1, 32>>>();
    k_minmax3<<<2048, 256>>>(x, h, c);
    k_params<<<1, 256>>>(Wi, bi, Wf, bf, Wo, bo, Wc, bc);
    k_quantc<<<4096, 256>>>(c);
    k_gemm<<<2048, 256>>>(x, h);
    k_p2<<<1, 1>>>();
    k_act<<<8192, 256>>>();
    k_p3<<<1, 1>>>();
    k_pre<<<8192, 256>>>();
    k_p4<<<1, 1>>>();
    k_cnext<<<8192, 256>>>(out_c);
    k_p5<<<1, 1>>>();
    k_hnext<<<8192, 256>>>(out_h);
}